// round 10
// baseline (speedup 1.0000x reference)
#include <cuda_runtime.h>
#include <math_constants.h>

#define HFEAT 200
#define WFEAT 320
#define HWFEAT (HFEAT * WFEAT)      // 64000 pixels
#define HW4 (HWFEAT / 4)            // 16000 pixel-quads
#define CFEAT 256
#define NROI 128
#define MSZ 14
#define NBIN (MSZ * MSZ)            // 196
#define NCB 16                      // fine channel blocks (16 channels each)
#define CPB 16
#define NSEED 8                     // seed rois per bin
#define CM_BLOCKS 250               // colmax blocks (4 phases x 16 quads each)
#define PREP_BLOCKS (NBIN + CM_BLOCKS)

// Scratch (static device arrays — no allocation)
__device__ __align__(16) float g_Mb[HWFEAT * NCB];   // per-pixel 16-ch block maxes (4 MB)
__device__ __align__(16) float g_best[NBIN];         // per-bin exact lower bound -> final max

// ---------------------------------------------------------------------------
__device__ __forceinline__ void atomicMaxFloat(float* addr, float val) {
    if (val >= 0.0f) {
        atomicMax((int*)addr, __float_as_int(val));
    } else {
        atomicMin((unsigned int*)addr, __float_as_uint(val));
    }
}

// ---------------------------------------------------------------------------
// Geometry: replicate the reference bilinear setup exactly
// (corner indices clamped FIRST, weights computed from clamped corners).
// ---------------------------------------------------------------------------
struct Geom {
    int o11, o12, o21, o22;
    float wy_lo, wy_hi, wx_lo, wx_hi;
    bool wok;   // weights are a convex combination (clamp did not trigger)
};

__device__ __forceinline__ Geom make_geom(const float* __restrict__ rois,
                                          int r, int s, int m, int n) {
    float r0 = __ldg(&rois[r * 4 + 0]);
    float r1 = __ldg(&rois[r * 4 + 1]);
    float r2 = __ldg(&rois[r * 4 + 2]);
    float r3 = __ldg(&rois[r * 4 + 3]);
    float sh = (r2 - r0) / 14.0f;
    float sw = (r3 - r1) / 14.0f;
    float fy = (s >> 1) ? (2.0f / 3.0f) : (1.0f / 3.0f);
    float fx = (s & 1)  ? (2.0f / 3.0f) : (1.0f / 3.0f);
    float y = (r0 + sh * (float)m) + sh * fy;
    float x = (r1 + sw * (float)n) + sw * fx;

    int yf = (int)floorf(y);
    int xf = (int)floorf(x);
    int y1c = min(max(yf, 0), HFEAT - 1);
    int y2c = min(max(yf + 1, 0), HFEAT - 1);
    int x1c = min(max(xf, 0), WFEAT - 1);
    int x2c = min(max(xf + 1, 0), WFEAT - 1);

    Geom g;
    g.wy_lo = y - (float)y1c;
    g.wy_hi = (float)y2c - y;
    g.wx_lo = x - (float)x1c;
    g.wx_hi = (float)x2c - x;
    g.wok = (g.wy_lo >= 0.0f) && (g.wy_lo <= 1.0f) && (g.wy_hi >= 0.0f) && (g.wy_hi <= 1.0f) &&
            (g.wx_lo >= 0.0f) && (g.wx_lo <= 1.0f) && (g.wx_hi >= 0.0f) && (g.wx_hi <= 1.0f);
    g.o11 = y1c * WFEAT + x1c;
    g.o12 = y1c * WFEAT + x2c;
    g.o21 = y2c * WFEAT + x1c;
    g.o22 = y2c * WFEAT + x2c;
    return g;
}

__device__ __forceinline__ float bilin(const float* __restrict__ base, const Geom& g) {
    float a = __ldg(base + g.o11);
    float b = __ldg(base + g.o12);
    float c = __ldg(base + g.o21);
    float d = __ldg(base + g.o22);
    return g.wy_hi * (g.wx_hi * a + g.wx_lo * b) +
           g.wy_lo * (g.wx_hi * c + g.wx_lo * d);
}

// ---------------------------------------------------------------------------
// Fused prep. Blocks [0,196) = seed (launched first; scattered gathers
// overlap colmax streaming). Blocks [196,446) = colmax, each running 4
// phases of (16 cb x 16 quads) through a smem transpose -> 446 total blocks
// = one wave, no tail (R9's 1196-block grid had a 12-block wave-2 tail).
// Seed: warp w exactly evaluates (roi w, sub 0) over all 256 channels;
// plain store into g_best (single writer -> deterministic on every replay).
// ---------------------------------------------------------------------------
__global__ void __launch_bounds__(256) k_prep(const float4* __restrict__ f4,
                                              const float* __restrict__ f,
                                              const float* __restrict__ rois) {
    __shared__ float s[64][NCB + 1];
    __shared__ float sred[NSEED];

    int bx = blockIdx.x;
    if (bx < NBIN) {
        // ---- seed ----
        int bin  = bx;
        int w    = threadIdx.x >> 5;
        int lane = threadIdx.x & 31;
        int m = bin / MSZ;
        int n = bin - m * MSZ;

        Geom g = make_geom(rois, w, 0, m, n);
        float vmax = -CUDART_INF_F;
#pragma unroll
        for (int ci = 0; ci < CFEAT / 32; ci++)
            vmax = fmaxf(vmax, bilin(f + (size_t)(ci * 32 + lane) * HWFEAT, g));
#pragma unroll
        for (int o = 16; o; o >>= 1)
            vmax = fmaxf(vmax, __shfl_xor_sync(0xffffffffu, vmax, o));
        if (lane == 0) sred[w] = vmax;
        __syncthreads();
        if (threadIdx.x == 0) {
            float b = sred[0];
#pragma unroll
            for (int k = 1; k < NSEED; k++) b = fmaxf(b, sred[k]);
            g_best[bin] = b;
        }
    } else {
        // ---- colmax: 4 phases of 16 cb x 16 quads ----
        int cbx = bx - NBIN;                // 0..249
        int qi = threadIdx.x & 15;
        int cb = threadIdx.x >> 4;

#pragma unroll
        for (int ph = 0; ph < 4; ph++) {
            int qg = (cbx * 4 + ph) * 16 + qi;   // global quad 0..15999

            const float4* p = f4 + (size_t)(cb * CPB) * HW4 + qg;
            float4 m = make_float4(-CUDART_INF_F, -CUDART_INF_F, -CUDART_INF_F, -CUDART_INF_F);
#pragma unroll
            for (int j = 0; j < CPB; j++) {
                float4 v = __ldg(p + (size_t)j * HW4);
                m.x = fmaxf(m.x, v.x); m.y = fmaxf(m.y, v.y);
                m.z = fmaxf(m.z, v.z); m.w = fmaxf(m.w, v.w);
            }
            if (ph) __syncthreads();            // smem reuse guard
            int lpx = qi * 4;
            s[lpx + 0][cb] = m.x;
            s[lpx + 1][cb] = m.y;
            s[lpx + 2][cb] = m.z;
            s[lpx + 3][cb] = m.w;
            __syncthreads();

            // coalesced g_Mb store: 64 px * 16 cb = 256 float4, one/thread
            int px  = threadIdx.x >> 2;
            int cb0 = (threadIdx.x & 3) * 4;
            float4 o = make_float4(s[px][cb0], s[px][cb0 + 1],
                                   s[px][cb0 + 2], s[px][cb0 + 3]);
            reinterpret_cast<float4*>(
                g_Mb + ((size_t)(cbx * 4 + ph) * 64) * NCB)[threadIdx.x] = o;
        }
    }
}

// ---------------------------------------------------------------------------
// Screened pass (R7 shape — measured good): one warp per candidate, grid
// (196, 64). Lanes 0..15 compute per-channel-block upper bounds from g_Mb
// (convex combination => valid bound; clamp case forces full eval). Only
// blocks whose bound beats the seeded exact best are evaluated, two blocks
// at a time across the warp. Per-block eval granularity is load-bearing.
// g_best holds only exact achieved values => pruning exact & deterministic.
// ---------------------------------------------------------------------------
__global__ void __launch_bounds__(256) k_points(const float* __restrict__ f,
                                                const float* __restrict__ rois) {
    int bin  = blockIdx.x;                          // 0..195
    int cand = blockIdx.y * 8 + (threadIdx.x >> 5); // 0..511
    int lane = threadIdx.x & 31;
    int m = bin / MSZ;
    int n = bin - m * MSZ;

    Geom g = make_geom(rois, cand >> 2, cand & 3, m, n);
    float best = __ldcg(&g_best[bin]);   // seeded exact lower bound

    bool need = false;
    if (lane < NCB) {
        float m11 = __ldg(&g_Mb[(size_t)g.o11 * NCB + lane]);
        float m12 = __ldg(&g_Mb[(size_t)g.o12 * NCB + lane]);
        float m21 = __ldg(&g_Mb[(size_t)g.o21 * NCB + lane]);
        float m22 = __ldg(&g_Mb[(size_t)g.o22 * NCB + lane]);
        float ub = g.wy_hi * (g.wx_hi * m11 + g.wx_lo * m12) +
                   g.wy_lo * (g.wx_hi * m21 + g.wx_lo * m22);
        need = ub > best;
    }
    unsigned mask = __ballot_sync(0xffffffffu, need) & 0xFFFFu;
    if (!g.wok) mask = 0xFFFFu;
    if (!mask) return;

    float vmax = -CUDART_INF_F;
    while (mask) {
        int cb0 = __ffs(mask) - 1;
        mask &= mask - 1;
        int cb1 = cb0;
        if (mask) { cb1 = __ffs(mask) - 1; mask &= mask - 1; }
        int cb = (lane < 16) ? cb0 : cb1;
        const float* fc = f + (size_t)(cb * CPB + (lane & 15)) * HWFEAT;
        vmax = fmaxf(vmax, bilin(fc, g));
    }
#pragma unroll
    for (int o = 16; o; o >>= 1)
        vmax = fmaxf(vmax, __shfl_xor_sync(0xffffffffu, vmax, o));
    if (lane == 0) atomicMaxFloat(&g_best[bin], vmax);
}

// ---------------------------------------------------------------------------
// Broadcast g_best[196] to out[R, C, 14, 14]: 784 blocks, 8 float4/thread.
// ---------------------------------------------------------------------------
__global__ void __launch_bounds__(256) k_bcast(float4* __restrict__ out) {
    __shared__ float4 sb[NBIN / 4];
    if (threadIdx.x < NBIN / 4)
        sb[threadIdx.x] = reinterpret_cast<const float4*>(g_best)[threadIdx.x];
    __syncthreads();
    int base = blockIdx.x * 2048 + threadIdx.x;
#pragma unroll
    for (int k = 0; k < 8; k++) {
        int i = base + k * 256;
        out[i] = sb[i % (NBIN / 4)];
    }
}

// ---------------------------------------------------------------------------
extern "C" void kernel_launch(void* const* d_in, const int* in_sizes, int n_in,
                              void* d_out, int out_size) {
    const float* feature = (const float*)d_in[0];   // [1,256,200,320] f32
    const float* rois    = (const float*)d_in[1];   // [128,4] f32
    float* out           = (float*)d_out;           // [128,256,14,14] f32

    // Fused seed + colmax, single wave (446 blocks)
    k_prep<<<PREP_BLOCKS, 256>>>((const float4*)feature, feature, rois);

    // Fine-screened pass: warp per candidate, per-block eval
    dim3 g2(NBIN, 64);
    k_points<<<g2, 256>>>(feature, rois);

    // Broadcast result: out_size/4 = 1605632 = 784 * 2048
    k_bcast<<<784, 256>>>((float4*)out);
}

// round 13
// speedup vs baseline: 1.8484x; 1.8484x over previous
#include <cuda_runtime.h>
#include <math_constants.h>

#define HFEAT 200
#define WFEAT 320
#define HWFEAT (HFEAT * WFEAT)      // 64000 pixels
#define HW4 (HWFEAT / 4)            // 16000 pixel-quads
#define CFEAT 256
#define NROI 128
#define MSZ 14
#define NBIN (MSZ * MSZ)            // 196
#define NCB 16                      // channel blocks (16 channels each)
#define CPB 16
#define NCAND (NROI * 4)            // 512 candidate points per bin
#define NSEED 8                     // rois used for seeding

// Scratch (static device arrays — no allocation)
__device__ __align__(16) float g_Mb[HWFEAT * NCB];   // [pix][cb] per-pixel 16-ch maxes (4 MB)
__device__ __align__(16) float g_best[NBIN];         // per-bin running exact max

// ---------------------------------------------------------------------------
__device__ __forceinline__ void atomicMaxFloat(float* addr, float val) {
    if (val >= 0.0f) {
        atomicMax((int*)addr, __float_as_int(val));
    } else {
        atomicMin((unsigned int*)addr, __float_as_uint(val));
    }
}

// ---------------------------------------------------------------------------
// Geometry: replicate the reference bilinear setup exactly
// (corner indices clamped FIRST, weights computed from clamped corners).
// ---------------------------------------------------------------------------
struct Geom {
    int o11, o12, o21, o22;
    float wy_lo, wy_hi, wx_lo, wx_hi;
    bool wok;   // weights form a convex combination (clamp did not trigger)
};

__device__ __forceinline__ Geom make_geom(const float* __restrict__ rois,
                                          int r, int s, int m, int n) {
    float r0 = __ldg(&rois[r * 4 + 0]);
    float r1 = __ldg(&rois[r * 4 + 1]);
    float r2 = __ldg(&rois[r * 4 + 2]);
    float r3 = __ldg(&rois[r * 4 + 3]);
    float sh = (r2 - r0) / 14.0f;
    float sw = (r3 - r1) / 14.0f;
    float fy = (s >> 1) ? (2.0f / 3.0f) : (1.0f / 3.0f);
    float fx = (s & 1)  ? (2.0f / 3.0f) : (1.0f / 3.0f);
    float y = (r0 + sh * (float)m) + sh * fy;
    float x = (r1 + sw * (float)n) + sw * fx;

    int yf = (int)floorf(y);
    int xf = (int)floorf(x);
    int y1c = min(max(yf, 0), HFEAT - 1);
    int y2c = min(max(yf + 1, 0), HFEAT - 1);
    int x1c = min(max(xf, 0), WFEAT - 1);
    int x2c = min(max(xf + 1, 0), WFEAT - 1);

    Geom g;
    g.wy_lo = y - (float)y1c;
    g.wy_hi = (float)y2c - y;
    g.wx_lo = x - (float)x1c;
    g.wx_hi = (float)x2c - x;
    g.wok = (g.wy_lo >= 0.0f) && (g.wy_lo <= 1.0f) && (g.wy_hi >= 0.0f) && (g.wy_hi <= 1.0f) &&
            (g.wx_lo >= 0.0f) && (g.wx_lo <= 1.0f) && (g.wx_hi >= 0.0f) && (g.wx_hi <= 1.0f);
    g.o11 = y1c * WFEAT + x1c;
    g.o12 = y1c * WFEAT + x2c;
    g.o21 = y2c * WFEAT + x1c;
    g.o22 = y2c * WFEAT + x2c;
    return g;
}

__device__ __forceinline__ float bilin(const float* __restrict__ base, const Geom& g) {
    float a = __ldg(base + g.o11);
    float b = __ldg(base + g.o12);
    float c = __ldg(base + g.o21);
    float d = __ldg(base + g.o22);
    return g.wy_hi * (g.wx_hi * a + g.wx_lo * b) +
           g.wy_lo * (g.wx_hi * c + g.wx_lo * d);
}

// ---------------------------------------------------------------------------
// Pass 1: per-pixel 16-channel-block maxes. (exact R7 configuration)
// grid = 1000 blocks; block = 256 threads = 16 cb x 16 pixel-quads.
// Loads: per (cb,j) each 16-thread group reads 256B contiguous float4s.
// Stores: block-local smem transpose -> one coalesced 4KB float4 burst into
// g_Mb[pix][16]. Also initializes g_best (block 0).
// ---------------------------------------------------------------------------
__global__ void __launch_bounds__(256) k_colmax(const float4* __restrict__ f4) {
    __shared__ float s[64][NCB + 1];    // +1 pad: kill store bank conflicts

    if (blockIdx.x == 0 && threadIdx.x < NBIN)
        g_best[threadIdx.x] = -CUDART_INF_F;

    int qi = threadIdx.x & 15;          // quad within block (0..15)
    int cb = threadIdx.x >> 4;          // channel block (0..15)
    int pg = blockIdx.x * 16 + qi;      // global pixel quad (0..15999)

    const float4* p = f4 + (size_t)(cb * CPB) * HW4 + pg;
    float4 m = make_float4(-CUDART_INF_F, -CUDART_INF_F, -CUDART_INF_F, -CUDART_INF_F);
#pragma unroll
    for (int j = 0; j < CPB; j++) {
        float4 v = __ldg(p + (size_t)j * HW4);
        m.x = fmaxf(m.x, v.x); m.y = fmaxf(m.y, v.y);
        m.z = fmaxf(m.z, v.z); m.w = fmaxf(m.w, v.w);
    }
    int lpx = qi * 4;                   // local pixel 0..63
    s[lpx + 0][cb] = m.x;
    s[lpx + 1][cb] = m.y;
    s[lpx + 2][cb] = m.z;
    s[lpx + 3][cb] = m.w;
    __syncthreads();

    // write 64 px * 16 cb = 256 float4, one per thread, coalesced
    int px  = threadIdx.x >> 2;         // 0..63
    int cb0 = (threadIdx.x & 3) * 4;    // 0,4,8,12
    float4 o = make_float4(s[px][cb0], s[px][cb0 + 1], s[px][cb0 + 2], s[px][cb0 + 3]);
    float4* dst = reinterpret_cast<float4*>(g_Mb + ((size_t)blockIdx.x * 64) * NCB);
    dst[threadIdx.x] = o;
}

// ---------------------------------------------------------------------------
// Seed pass: exact evaluation of NSEED candidate points per bin, publishing
// tight exact lower bounds into g_best before the screened pass runs.
// grid = 196 blocks x 8 warps; warp w -> (roi w, sub 0). 32 lanes x 8 iters
// cover the 256 channels.  (exact R7 configuration)
// ---------------------------------------------------------------------------
__global__ void __launch_bounds__(NSEED * 32) k_seed(const float* __restrict__ f,
                                                     const float* __restrict__ rois) {
    int bin  = blockIdx.x;
    int w    = threadIdx.x >> 5;        // roi 0..NSEED-1
    int lane = threadIdx.x & 31;
    int m = bin / MSZ;
    int n = bin - m * MSZ;

    Geom g = make_geom(rois, w, 0, m, n);

    float vmax = -CUDART_INF_F;
#pragma unroll
    for (int ci = 0; ci < CFEAT / 32; ci++) {
        const float* fc = f + (size_t)(ci * 32 + lane) * HWFEAT;
        vmax = fmaxf(vmax, bilin(fc, g));
    }
#pragma unroll
    for (int o = 16; o; o >>= 1)
        vmax = fmaxf(vmax, __shfl_xor_sync(0xffffffffu, vmax, o));
    if (lane == 0) atomicMaxFloat(&g_best[bin], vmax);
}

// ---------------------------------------------------------------------------
// Screened point pass: one warp per (bin, candidate). (exact R7 configuration)
// Lanes 0..15 bound the 16 channel blocks via bilinear interp of per-pixel
// block maxes (convex combination => valid upper bound; clamp forces eval).
// Surviving blocks evaluated two-at-a-time across the full warp.
// g_best holds only exact values => pruning is exact & deterministic.
// ---------------------------------------------------------------------------
__global__ void __launch_bounds__(256) k_points(const float* __restrict__ f,
                                                const float* __restrict__ rois) {
    int bin  = blockIdx.x;                          // 0..195
    int cand = blockIdx.y * 8 + (threadIdx.x >> 5); // 0..511
    int lane = threadIdx.x & 31;

    int r = cand >> 2;
    int s = cand & 3;
    int m = bin / MSZ;
    int n = bin - m * MSZ;

    Geom g = make_geom(rois, r, s, m, n);

    float best = __ldg(&g_best[bin]);   // seeded exact lower bound

    bool need = false;
    if (lane < NCB) {
        float m11 = __ldg(&g_Mb[(size_t)g.o11 * NCB + lane]);
        float m12 = __ldg(&g_Mb[(size_t)g.o12 * NCB + lane]);
        float m21 = __ldg(&g_Mb[(size_t)g.o21 * NCB + lane]);
        float m22 = __ldg(&g_Mb[(size_t)g.o22 * NCB + lane]);
        float ub = g.wy_hi * (g.wx_hi * m11 + g.wx_lo * m12) +
                   g.wy_lo * (g.wx_hi * m21 + g.wx_lo * m22);
        need = (!g.wok) || (ub > best);
    }
    unsigned mask = __ballot_sync(0xffffffffu, need);
    if (!mask) return;

    float vmax = -CUDART_INF_F;
    while (mask) {
        int cb0 = __ffs(mask) - 1;
        mask &= mask - 1;
        int cb1 = cb0;
        if (mask) { cb1 = __ffs(mask) - 1; mask &= mask - 1; }
        int cb = (lane < 16) ? cb0 : cb1;
        const float* fc = f + (size_t)(cb * CPB + (lane & 15)) * HWFEAT;
        vmax = fmaxf(vmax, bilin(fc, g));
    }
#pragma unroll
    for (int o = 16; o; o >>= 1)
        vmax = fmaxf(vmax, __shfl_xor_sync(0xffffffffu, vmax, o));
    if (lane == 0) atomicMaxFloat(&g_best[bin], vmax);
}

// ---------------------------------------------------------------------------
// Broadcast g_best[196] to out[R, C, 14, 14]. THE ONLY CHANGE vs R7:
// 784 blocks x 256 threads x 8 float4 stores (was 6272 tiny blocks with
// per-element modulo; 7.6us issue-bound). i % 49 is precomputed once per
// thread and advanced by constant steps.
// out_size/4 = 1605632 = 784 * 2048; 2048 = 8 * 256.
// ---------------------------------------------------------------------------
__global__ void __launch_bounds__(256) k_bcast(float4* __restrict__ out) {
    __shared__ float4 sb[NBIN / 4];     // 49 float4
    if (threadIdx.x < NBIN / 4)
        sb[threadIdx.x] = reinterpret_cast<const float4*>(g_best)[threadIdx.x];
    __syncthreads();
    int base = blockIdx.x * 2048 + threadIdx.x;
    int idx  = base % (NBIN / 4);       // one division per thread
#pragma unroll
    for (int k = 0; k < 8; k++) {
        out[base + k * 256] = sb[idx];
        idx += 256 % (NBIN / 4);        // 256 % 49 = 11 (compile-time)
        if (idx >= NBIN / 4) idx -= NBIN / 4;
    }
}

// ---------------------------------------------------------------------------
extern "C" void kernel_launch(void* const* d_in, const int* in_sizes, int n_in,
                              void* d_out, int out_size) {
    const float* feature = (const float*)d_in[0];   // [1,256,200,320] f32
    const float* rois    = (const float*)d_in[1];   // [128,4] f32
    float* out           = (float*)d_out;           // [128,256,14,14] f32

    // Pass 1: per-pixel 16-channel block maxes (+ g_best init)
    k_colmax<<<HW4 / 16, 256>>>((const float4*)feature);

    // Seed: exact per-bin lower bounds from 8 candidates
    k_seed<<<NBIN, NSEED * 32>>>(feature, rois);

    // Screened pass over all (bin, candidate) pairs
    dim3 g2(NBIN, NCAND / 8);
    k_points<<<g2, 256>>>(feature, rois);

    // Broadcast result
    k_bcast<<<784, 256>>>((float4*)out);
}